// round 16
// baseline (speedup 1.0000x reference)
#include <cuda_runtime.h>
#include <cstdint>

// SNN Leaky forward:  mem = 0.5*mem + x_t - spk;  spk = (mem > 1) ? 1 : 0
// x: [128, 64*4096] f32 -> spk same shape.
//
// R16: the replay loop is end-to-end mixed-R/W DRAM bound (268MB @
// ~5.7TB/s = 47us, invariant across 10 configs; evict_last residency is
// dead -- persisting-L2 limit defaults to 0 and may not be changed).
// Last lever: write-burst granularity. Stage 8 timesteps of spikes in
// SMEM and emit 2KB contiguous cp.async.bulk stores (async engine,
// double-buffered) instead of warp-granular STG.128, testing whether the
// DRAM controller schedules large contiguous write bursts better in a
// 50/50 mixed stream. Loads keep the proven R5 path (ldcs unroll-8 +
// L2 bulk prefetch).

#define T_STEPS 128
#define BN4 65536                 // (64*4096)/4 float4 columns per timestep
#define BLOCK 128                 // 128 thr x float4 = 2KB per CTA-timestep
#define NCTA (BN4 / BLOCK)        // 512
#define PF_DIST 8
#define PF_BYTES (BLOCK * 16)     // 2KB slab per CTA per timestep

__device__ __forceinline__ uint32_t s2u(const void* p) {
    return (uint32_t)__cvta_generic_to_shared(p);
}
__device__ __forceinline__ void l2_prefetch(const void* p, uint32_t bytes) {
    asm volatile("cp.async.bulk.prefetch.L2.global [%0], %1;"
                 :: "l"(p), "r"(bytes) : "memory");
}
__device__ __forceinline__ void bulk_st(void* gdst, uint32_t ssrc, uint32_t bytes) {
    asm volatile("cp.async.bulk.global.shared::cta.bulk_group [%0], [%1], %2;"
                 :: "l"(gdst), "r"(ssrc), "r"(bytes) : "memory");
}

__global__ __launch_bounds__(BLOCK) void snn_leaky_kernel(
    const float4* __restrict__ x4, float4* __restrict__ o4)
{
    __shared__ alignas(128) float4 buf[2][8][BLOCK];   // 32KB, double buffer

    const int tid = threadIdx.x;
    const int idx = blockIdx.x * BLOCK + tid;          // 0..BN4-1
    const float4* xp = x4 + idx;
    float4* ob = o4 + blockIdx.x * BLOCK;              // CTA slab base
    const float4* pf_base = x4 + blockIdx.x * BLOCK;

    // prologue: prefetch timesteps 0..PF_DIST-1
    if (tid == 0) {
#pragma unroll
        for (int t = 0; t < PF_DIST; t++)
            l2_prefetch(pf_base + (size_t)t * BN4, PF_BYTES);
    }

    float4 mem = make_float4(0.f, 0.f, 0.f, 0.f);
    float4 spk = make_float4(0.f, 0.f, 0.f, 0.f);

    for (int t = 0; t < T_STEPS; t += 8) {
        const int p = (t >> 3) & 1;

        // make sure buffer p's previous bulk-store group has drained
        // (groups: one per batch; allow only the most recent to be pending)
        if (tid == 0 && t >= 16)
            asm volatile("cp.async.bulk.wait_group.read 1;" ::: "memory");
        __syncthreads();

        // keep the async prefetch engine PF_DIST steps ahead
        if (tid == 0 && t + PF_DIST < T_STEPS) {
#pragma unroll
            for (int u = 0; u < 8; u++)
                l2_prefetch(pf_base + (size_t)(t + PF_DIST + u) * BN4, PF_BYTES);
        }

        // front-batch 8 independent loads
        float4 a[8];
#pragma unroll
        for (int u = 0; u < 8; u++)
            a[u] = __ldcs(xp + (size_t)(t + u) * BN4);

        // 8 recurrence steps; spikes staged to SMEM
#pragma unroll
        for (int u = 0; u < 8; u++) {
            mem.x = 0.5f * mem.x + a[u].x - spk.x;
            mem.y = 0.5f * mem.y + a[u].y - spk.y;
            mem.z = 0.5f * mem.z + a[u].z - spk.z;
            mem.w = 0.5f * mem.w + a[u].w - spk.w;

            spk.x = (mem.x > 1.0f) ? 1.0f : 0.0f;
            spk.y = (mem.y > 1.0f) ? 1.0f : 0.0f;
            spk.z = (mem.z > 1.0f) ? 1.0f : 0.0f;
            spk.w = (mem.w > 1.0f) ? 1.0f : 0.0f;

            buf[p][u][tid] = spk;
        }

        // publish SMEM to the async proxy, then emit 8 x 2KB bulk stores
        asm volatile("fence.proxy.async.shared::cta;" ::: "memory");
        __syncthreads();
        if (tid == 0) {
#pragma unroll
            for (int u = 0; u < 8; u++)
                bulk_st(ob + (size_t)(t + u) * BN4, s2u(&buf[p][u][0]),
                        BLOCK * 16);
            asm volatile("cp.async.bulk.commit_group;" ::: "memory");
        }
    }

    // drain all outstanding bulk stores before exit
    if (tid == 0)
        asm volatile("cp.async.bulk.wait_group.read 0;" ::: "memory");
}

extern "C" void kernel_launch(void* const* d_in, const int* in_sizes, int n_in,
                              void* d_out, int out_size)
{
    const float4* x4 = (const float4*)d_in[0];
    float4* o4 = (float4*)d_out;
    snn_leaky_kernel<<<NCTA, BLOCK>>>(x4, o4);
}

// round 17
// speedup vs baseline: 1.0054x; 1.0054x over previous
#include <cuda_runtime.h>
#include <cstdint>

// SNN Leaky forward:  mem = 0.5*mem + x_t - spk;  spk = (mem > 1) ? 1 : 0
// x: [128, 64*4096] f32 -> spk same shape. Pure HBM streaming.
//
// FINAL (== R5, measured best dur 47.07us). The timed replay loop is
// end-to-end DRAM-traffic bound: 268MB irreducible (134 read + 134
// write, no reuse) at ~5.7TB/s sustained mixed-stream rate = ~47us.
// Falsified levers (12 configs, dur invariant 47.1-49.9):
//   MLP depth, warp count, TMA load pipeline, burst phase-split,
//   evict_last residency (in/out/both; persisting-L2 carveout is 0 and
//   may not be changed), TMA bulk 2KB write bursts.
// Config: float4/thread, unroll-8 front-batched __ldcs (56KB in-flight
// /SM), __stcs streaming stores, cp.async.bulk.prefetch.L2 16 steps
// ahead (16MB L2 window), block=64/grid=1024 (1.2% wave imbalance).

#define T_STEPS 128
#define BN4 65536                 // (64*4096)/4 float4 columns per timestep
#define BLOCK 64
#define PF_DIST 16                // timesteps of prefetch lead
#define PF_BYTES (BLOCK * 16)     // 1KB slab per CTA per timestep

__device__ __forceinline__ void l2_prefetch(const void* p, uint32_t bytes) {
    asm volatile("cp.async.bulk.prefetch.L2.global [%0], %1;"
                 :: "l"(p), "r"(bytes) : "memory");
}

__global__ __launch_bounds__(BLOCK) void snn_leaky_kernel(
    const float4* __restrict__ x4, float4* __restrict__ o4)
{
    const int idx = blockIdx.x * BLOCK + threadIdx.x;   // 0..BN4-1
    const float4* xp = x4 + idx;
    float4* op = o4 + idx;

    // CTA's contiguous 1KB slab base for prefetching
    const float4* pf_base = x4 + blockIdx.x * BLOCK;

    // prologue: prefetch timesteps 0..PF_DIST-1
    if (threadIdx.x == 0) {
#pragma unroll
        for (int t = 0; t < PF_DIST; t++)
            l2_prefetch(pf_base + (size_t)t * BN4, PF_BYTES);
    }

    float4 mem = make_float4(0.f, 0.f, 0.f, 0.f);
    float4 spk = make_float4(0.f, 0.f, 0.f, 0.f);

    for (int t = 0; t < T_STEPS; t += 8) {
        // prefetch the batch PF_DIST ahead (1 thread, fire-and-forget)
        if (threadIdx.x == 0 && t + PF_DIST < T_STEPS) {
#pragma unroll
            for (int u = 0; u < 8; u++)
                l2_prefetch(pf_base + (size_t)(t + PF_DIST + u) * BN4, PF_BYTES);
        }

        // front-batch 8 independent loads (mostly L2 hits via prefetch)
        float4 a[8];
#pragma unroll
        for (int u = 0; u < 8; u++)
            a[u] = __ldcs(xp + (size_t)(t + u) * BN4);

#pragma unroll
        for (int u = 0; u < 8; u++) {
            mem.x = 0.5f * mem.x + a[u].x - spk.x;
            mem.y = 0.5f * mem.y + a[u].y - spk.y;
            mem.z = 0.5f * mem.z + a[u].z - spk.z;
            mem.w = 0.5f * mem.w + a[u].w - spk.w;

            spk.x = (mem.x > 1.0f) ? 1.0f : 0.0f;
            spk.y = (mem.y > 1.0f) ? 1.0f : 0.0f;
            spk.z = (mem.z > 1.0f) ? 1.0f : 0.0f;
            spk.w = (mem.w > 1.0f) ? 1.0f : 0.0f;

            __stcs(op + (size_t)(t + u) * BN4, spk);
        }
    }
}

extern "C" void kernel_launch(void* const* d_in, const int* in_sizes, int n_in,
                              void* d_out, int out_size)
{
    const float4* x4 = (const float4*)d_in[0];
    float4* o4 = (float4*)d_out;
    snn_leaky_kernel<<<BN4 / BLOCK, BLOCK>>>(x4, o4);
}